// round 1
// baseline (speedup 1.0000x reference)
#include <cuda_runtime.h>

#define B_ 4
#define S_ 2048
#define E_ 1024
#define H_ 16
#define D_ 64
#define MTOT (B_*S_)   // 8192

// Scratch (device globals: allocation-free rule)
__device__ float g_Q[B_*S_*E_];
__device__ float g_K[B_*S_*E_];
__device__ float g_V[B_*S_*E_];
__device__ float g_Ctx[B_*S_*E_];

// ---------------------------------------------------------------------------
// SGEMM (NT): C[m,n] = sum_k A[m,k] * B[n,k] (+ bias[n])
// 128x128 block tile, BK=8, 256 threads, 8x8 per-thread microtile.
// M, N divisible by 128; K divisible by 8 (holds: 8192/1024/1024).
// ---------------------------------------------------------------------------
__global__ __launch_bounds__(256) void sgemm_nt_kernel(
    const float* __restrict__ A, const float* __restrict__ Bm,
    const float* __restrict__ bias, float* __restrict__ C,
    int M, int N, int K)
{
    __shared__ float As[8 * 128];
    __shared__ float Bs[8 * 128];

    const int tid = threadIdx.x;
    const int bm = blockIdx.y, bn = blockIdx.x;

    const int ldrow = tid >> 1;            // 0..127
    const int ldc4  = (tid & 1) * 4;       // 0 or 4

    const float* Ap = A + (size_t)(bm * 128 + ldrow) * K + ldc4;
    const float* Bp = Bm + (size_t)(bn * 128 + ldrow) * K + ldc4;

    const int tm = tid >> 4;               // 0..15
    const int tn = tid & 15;               // 0..15

    float acc[8][8];
#pragma unroll
    for (int i = 0; i < 8; i++)
#pragma unroll
        for (int j = 0; j < 8; j++) acc[i][j] = 0.f;

    for (int kt = 0; kt < K; kt += 8) {
        float4 av = *(const float4*)(Ap + kt);
        float4 bv = *(const float4*)(Bp + kt);
        __syncthreads();
        As[(ldc4 + 0) * 128 + ldrow] = av.x;
        As[(ldc4 + 1) * 128 + ldrow] = av.y;
        As[(ldc4 + 2) * 128 + ldrow] = av.z;
        As[(ldc4 + 3) * 128 + ldrow] = av.w;
        Bs[(ldc4 + 0) * 128 + ldrow] = bv.x;
        Bs[(ldc4 + 1) * 128 + ldrow] = bv.y;
        Bs[(ldc4 + 2) * 128 + ldrow] = bv.z;
        Bs[(ldc4 + 3) * 128 + ldrow] = bv.w;
        __syncthreads();

#pragma unroll
        for (int kk = 0; kk < 8; kk++) {
            float a[8], b[8];
            *(float4*)&a[0] = *(const float4*)&As[kk * 128 + tm * 4];
            *(float4*)&a[4] = *(const float4*)&As[kk * 128 + tm * 4 + 64];
            *(float4*)&b[0] = *(const float4*)&Bs[kk * 128 + tn * 4];
            *(float4*)&b[4] = *(const float4*)&Bs[kk * 128 + tn * 4 + 64];
#pragma unroll
            for (int i = 0; i < 8; i++)
#pragma unroll
                for (int j = 0; j < 8; j++)
                    acc[i][j] = fmaf(a[i], b[j], acc[i][j]);
        }
    }

#pragma unroll
    for (int ih = 0; ih < 2; ih++)
#pragma unroll
        for (int i = 0; i < 4; i++) {
            int row = bm * 128 + tm * 4 + ih * 64 + i;
#pragma unroll
            for (int jh = 0; jh < 2; jh++) {
                int col = bn * 128 + tn * 4 + jh * 64;
                float4 o = make_float4(acc[ih * 4 + i][jh * 4 + 0],
                                       acc[ih * 4 + i][jh * 4 + 1],
                                       acc[ih * 4 + i][jh * 4 + 2],
                                       acc[ih * 4 + i][jh * 4 + 3]);
                if (bias) {
                    o.x += bias[col + 0];
                    o.y += bias[col + 1];
                    o.z += bias[col + 2];
                    o.w += bias[col + 3];
                }
                *(float4*)&C[(size_t)row * N + col] = o;
            }
        }
}

// ---------------------------------------------------------------------------
// fp32 flash attention.
// Q/K/V stored as [B, S, E] = [B, S, H, D]; per (b,h) slice strided by E.
// BQ=64 query rows per block, BKV=64 keys per inner tile, 256 threads.
// Thread (ty,tx): ty owns 4 query rows (ty*4..), tx owns 4 score cols /
// 4 output dims (tx*4..). Row groups = 16 consecutive lanes -> shfl reduce.
// ---------------------------------------------------------------------------
#define BQ 64
#define BKV 64
#define KP 68   // K^T smem pitch (mult of 4 for float4 alignment)
// dynamic smem layout (floats):
//   Qs: [64][64]        @ 0      (4096)
//   Ks: [64 d][KP keys] @ 4096   (4352)
//   Vs: [64][64]        @ 8448   (4096)
//   Ps: [64][64]        @ 12544  (4096)
#define FLASH_SMEM_FLOATS (4096 + 64*KP + 4096 + 4096)

__global__ __launch_bounds__(256) void flash_fp32_kernel(
    const float* __restrict__ Q, const float* __restrict__ K,
    const float* __restrict__ V, float* __restrict__ O)
{
    extern __shared__ float sm[];
    float* Qs = sm;
    float* Ks = sm + 4096;
    float* Vs = Ks + 64 * KP;
    float* Ps = Vs + 4096;

    const int tid = threadIdx.x;
    const int ty = tid >> 4, tx = tid & 15;
    const int b = blockIdx.z, h = blockIdx.y;
    const int q0 = blockIdx.x * BQ;
    const int base = (b * S_) * E_ + h * D_;   // + s*E_ + d

    // Load + pre-scale Q tile (1/sqrt(D) = 0.125)
#pragma unroll
    for (int t = 0; t < 4; t++) {
        int f = tid + t * 256;
        int r = f >> 4, c = (f & 15) * 4;
        float4 v = *(const float4*)&Q[base + (q0 + r) * E_ + c];
        v.x *= 0.125f; v.y *= 0.125f; v.z *= 0.125f; v.w *= 0.125f;
        *(float4*)&Qs[r * 64 + c] = v;
    }

    float m[4], l[4], acc[4][4];
#pragma unroll
    for (int i = 0; i < 4; i++) {
        m[i] = -1e30f; l[i] = 0.f;
#pragma unroll
        for (int j = 0; j < 4; j++) acc[i][j] = 0.f;
    }

    for (int t0 = 0; t0 < S_; t0 += BKV) {
        __syncthreads();
        // Load K (transposed into Ks[d][key]) and V tiles
#pragma unroll
        for (int t = 0; t < 4; t++) {
            int f = tid + t * 256;
            int r = f >> 4, c = (f & 15) * 4;
            float4 kv = *(const float4*)&K[base + (t0 + r) * E_ + c];
            Ks[(c + 0) * KP + r] = kv.x;
            Ks[(c + 1) * KP + r] = kv.y;
            Ks[(c + 2) * KP + r] = kv.z;
            Ks[(c + 3) * KP + r] = kv.w;
            *(float4*)&Vs[r * 64 + c] =
                *(const float4*)&V[base + (t0 + r) * E_ + c];
        }
        __syncthreads();

        // Scores: s[i][j] = sum_d Qs[qy+i][d] * Ks[d][kx+j]
        float s4[4][4];
#pragma unroll
        for (int i = 0; i < 4; i++)
#pragma unroll
            for (int j = 0; j < 4; j++) s4[i][j] = 0.f;

#pragma unroll 8
        for (int d = 0; d < 64; d++) {
            float4 kf = *(const float4*)&Ks[d * KP + tx * 4];
            float q0v = Qs[(ty * 4 + 0) * 64 + d];
            float q1v = Qs[(ty * 4 + 1) * 64 + d];
            float q2v = Qs[(ty * 4 + 2) * 64 + d];
            float q3v = Qs[(ty * 4 + 3) * 64 + d];
            s4[0][0] = fmaf(q0v, kf.x, s4[0][0]); s4[0][1] = fmaf(q0v, kf.y, s4[0][1]);
            s4[0][2] = fmaf(q0v, kf.z, s4[0][2]); s4[0][3] = fmaf(q0v, kf.w, s4[0][3]);
            s4[1][0] = fmaf(q1v, kf.x, s4[1][0]); s4[1][1] = fmaf(q1v, kf.y, s4[1][1]);
            s4[1][2] = fmaf(q1v, kf.z, s4[1][2]); s4[1][3] = fmaf(q1v, kf.w, s4[1][3]);
            s4[2][0] = fmaf(q2v, kf.x, s4[2][0]); s4[2][1] = fmaf(q2v, kf.y, s4[2][1]);
            s4[2][2] = fmaf(q2v, kf.z, s4[2][2]); s4[2][3] = fmaf(q2v, kf.w, s4[2][3]);
            s4[3][0] = fmaf(q3v, kf.x, s4[3][0]); s4[3][1] = fmaf(q3v, kf.y, s4[3][1]);
            s4[3][2] = fmaf(q3v, kf.z, s4[3][2]); s4[3][3] = fmaf(q3v, kf.w, s4[3][3]);
        }

        // Online softmax (row group = 16 lanes, xor-shuffle width 16)
#pragma unroll
        for (int i = 0; i < 4; i++) {
            float mx = fmaxf(fmaxf(s4[i][0], s4[i][1]), fmaxf(s4[i][2], s4[i][3]));
            mx = fmaxf(mx, __shfl_xor_sync(0xffffffffu, mx, 8));
            mx = fmaxf(mx, __shfl_xor_sync(0xffffffffu, mx, 4));
            mx = fmaxf(mx, __shfl_xor_sync(0xffffffffu, mx, 2));
            mx = fmaxf(mx, __shfl_xor_sync(0xffffffffu, mx, 1));
            float mn = fmaxf(m[i], mx);
            float al = __expf(m[i] - mn);
            m[i] = mn;
            float p0 = __expf(s4[i][0] - mn);
            float p1 = __expf(s4[i][1] - mn);
            float p2 = __expf(s4[i][2] - mn);
            float p3 = __expf(s4[i][3] - mn);
            float rs = (p0 + p1) + (p2 + p3);
            rs += __shfl_xor_sync(0xffffffffu, rs, 8);
            rs += __shfl_xor_sync(0xffffffffu, rs, 4);
            rs += __shfl_xor_sync(0xffffffffu, rs, 2);
            rs += __shfl_xor_sync(0xffffffffu, rs, 1);
            l[i] = l[i] * al + rs;
            acc[i][0] *= al; acc[i][1] *= al; acc[i][2] *= al; acc[i][3] *= al;
            *(float4*)&Ps[(ty * 4 + i) * 64 + tx * 4] = make_float4(p0, p1, p2, p3);
        }
        __syncthreads();

        // O += P @ V
#pragma unroll 8
        for (int kk = 0; kk < 64; kk++) {
            float4 vf = *(const float4*)&Vs[kk * 64 + tx * 4];
            float p0 = Ps[(ty * 4 + 0) * 64 + kk];
            float p1 = Ps[(ty * 4 + 1) * 64 + kk];
            float p2 = Ps[(ty * 4 + 2) * 64 + kk];
            float p3 = Ps[(ty * 4 + 3) * 64 + kk];
            acc[0][0] = fmaf(p0, vf.x, acc[0][0]); acc[0][1] = fmaf(p0, vf.y, acc[0][1]);
            acc[0][2] = fmaf(p0, vf.z, acc[0][2]); acc[0][3] = fmaf(p0, vf.w, acc[0][3]);
            acc[1][0] = fmaf(p1, vf.x, acc[1][0]); acc[1][1] = fmaf(p1, vf.y, acc[1][1]);
            acc[1][2] = fmaf(p1, vf.z, acc[1][2]); acc[1][3] = fmaf(p1, vf.w, acc[1][3]);
            acc[2][0] = fmaf(p2, vf.x, acc[2][0]); acc[2][1] = fmaf(p2, vf.y, acc[2][1]);
            acc[2][2] = fmaf(p2, vf.z, acc[2][2]); acc[2][3] = fmaf(p2, vf.w, acc[2][3]);
            acc[3][0] = fmaf(p3, vf.x, acc[3][0]); acc[3][1] = fmaf(p3, vf.y, acc[3][1]);
            acc[3][2] = fmaf(p3, vf.z, acc[3][2]); acc[3][3] = fmaf(p3, vf.w, acc[3][3]);
        }
    }

    // Normalize + write ctx in [B,S,H,D] layout
#pragma unroll
    for (int i = 0; i < 4; i++) {
        float inv = 1.f / l[i];
        float4 o = make_float4(acc[i][0] * inv, acc[i][1] * inv,
                               acc[i][2] * inv, acc[i][3] * inv);
        *(float4*)&O[base + (q0 + ty * 4 + i) * E_ + tx * 4] = o;
    }
}

// ---------------------------------------------------------------------------
extern "C" void kernel_launch(void* const* d_in, const int* in_sizes, int n_in,
                              void* d_out, int out_size)
{
    const float* X  = (const float*)d_in[0];
    const float* Wq = (const float*)d_in[1];
    const float* Wk = (const float*)d_in[2];
    const float* Wv = (const float*)d_in[3];
    const float* Wo = (const float*)d_in[4];
    const float* bo = (const float*)d_in[5];
    float* out = (float*)d_out;

    float *Qp, *Kp, *Vp, *Cp;
    cudaGetSymbolAddress((void**)&Qp, g_Q);
    cudaGetSymbolAddress((void**)&Kp, g_K);
    cudaGetSymbolAddress((void**)&Vp, g_V);
    cudaGetSymbolAddress((void**)&Cp, g_Ctx);

    dim3 gemm_grid(E_ / 128, MTOT / 128);   // (8, 64)
    sgemm_nt_kernel<<<gemm_grid, 256>>>(X, Wq, nullptr, Qp, MTOT, E_, E_);
    sgemm_nt_kernel<<<gemm_grid, 256>>>(X, Wk, nullptr, Kp, MTOT, E_, E_);
    sgemm_nt_kernel<<<gemm_grid, 256>>>(X, Wv, nullptr, Vp, MTOT, E_, E_);

    int smem_bytes = FLASH_SMEM_FLOATS * (int)sizeof(float);   // 66560
    cudaFuncSetAttribute(flash_fp32_kernel,
                         cudaFuncAttributeMaxDynamicSharedMemorySize, smem_bytes);
    flash_fp32_kernel<<<dim3(S_ / BQ, H_, B_), 256, smem_bytes>>>(Qp, Kp, Vp, Cp);

    sgemm_nt_kernel<<<gemm_grid, 256>>>(Cp, Wo, bo, out, MTOT, E_, E_);
}

// round 2
// speedup vs baseline: 2.7475x; 2.7475x over previous
#include <cuda_runtime.h>
#include <cstdint>

#define B_ 4
#define S_ 2048
#define E_ 1024
#define H_ 16
#define D_ 64
#define MTOT (B_*S_)   // 8192

// Scratch (device globals: allocation-free rule)
__device__ float g_Q[B_*S_*E_];
__device__ float g_K[B_*S_*E_];
__device__ float g_V[B_*S_*E_];
__device__ float g_Ctx[B_*S_*E_];

// ---------------------------------------------------------------------------
// helpers
// ---------------------------------------------------------------------------
__device__ __forceinline__ uint32_t f2tf(float x) {
    uint32_t r;
    asm("cvt.rna.tf32.f32 %0, %1;" : "=r"(r) : "f"(x));
    return r;
}

__device__ __forceinline__ void mma_tf32(float* c, const uint32_t* a,
                                         uint32_t b0, uint32_t b1) {
    asm volatile(
        "mma.sync.aligned.m16n8k8.row.col.f32.tf32.tf32.f32 "
        "{%0,%1,%2,%3}, {%4,%5,%6,%7}, {%8,%9}, {%0,%1,%2,%3};"
        : "+f"(c[0]), "+f"(c[1]), "+f"(c[2]), "+f"(c[3])
        : "r"(a[0]), "r"(a[1]), "r"(a[2]), "r"(a[3]), "r"(b0), "r"(b1));
}

// ---------------------------------------------------------------------------
// tf32 GEMM (NT): C[m,n] = sum_k A[m,k]*B[n,k] (+ bias[n])
// CTA 128x128, BK=16, 256 thr (8 warps, 2x4 grid), warp tile 64x32.
// smem pitch 20 (mod 32 == 4): conflict-free 8row x 4col fragment reads.
// ---------------------------------------------------------------------------
#define GP 20
__global__ __launch_bounds__(256) void gemm_tf32_nt(
    const float* __restrict__ A, const float* __restrict__ Bm,
    const float* __restrict__ bias, float* __restrict__ C,
    int M, int N, int K)
{
    __shared__ float As[128 * GP];
    __shared__ float Bs[128 * GP];

    const int tid = threadIdx.x;
    const int warp = tid >> 5, lane = tid & 31;
    const int g = lane >> 2, q = lane & 3;
    const int wm = warp >> 2;          // 0..1
    const int wn = warp & 3;           // 0..3
    const int bm = blockIdx.y, bn = blockIdx.x;

    const int lrow = tid >> 1;
    const int lcol = (tid & 1) * 8;
    const float* Ap = A + (size_t)(bm * 128 + lrow) * K + lcol;
    const float* Bp = Bm + (size_t)(bn * 128 + lrow) * K + lcol;

    float acc[4][4][4];
#pragma unroll
    for (int i = 0; i < 4; i++)
#pragma unroll
        for (int j = 0; j < 4; j++)
#pragma unroll
            for (int t = 0; t < 4; t++) acc[i][j][t] = 0.f;

    for (int kt = 0; kt < K; kt += 16) {
        float4 a0 = *(const float4*)(Ap + kt);
        float4 a1 = *(const float4*)(Ap + kt + 4);
        float4 b0 = *(const float4*)(Bp + kt);
        float4 b1 = *(const float4*)(Bp + kt + 4);
        __syncthreads();
        {
            float* as = &As[lrow * GP + lcol];
            as[0] = __uint_as_float(f2tf(a0.x)); as[1] = __uint_as_float(f2tf(a0.y));
            as[2] = __uint_as_float(f2tf(a0.z)); as[3] = __uint_as_float(f2tf(a0.w));
            as[4] = __uint_as_float(f2tf(a1.x)); as[5] = __uint_as_float(f2tf(a1.y));
            as[6] = __uint_as_float(f2tf(a1.z)); as[7] = __uint_as_float(f2tf(a1.w));
            float* bs = &Bs[lrow * GP + lcol];
            bs[0] = __uint_as_float(f2tf(b0.x)); bs[1] = __uint_as_float(f2tf(b0.y));
            bs[2] = __uint_as_float(f2tf(b0.z)); bs[3] = __uint_as_float(f2tf(b0.w));
            bs[4] = __uint_as_float(f2tf(b1.x)); bs[5] = __uint_as_float(f2tf(b1.y));
            bs[6] = __uint_as_float(f2tf(b1.z)); bs[7] = __uint_as_float(f2tf(b1.w));
        }
        __syncthreads();

#pragma unroll
        for (int kh = 0; kh < 2; kh++) {
            const int k0 = kh * 8;
            uint32_t af[4][4];
#pragma unroll
            for (int i = 0; i < 4; i++) {
                int r = wm * 64 + i * 16 + g;
                af[i][0] = __float_as_uint(As[r * GP + k0 + q]);
                af[i][1] = __float_as_uint(As[(r + 8) * GP + k0 + q]);
                af[i][2] = __float_as_uint(As[r * GP + k0 + q + 4]);
                af[i][3] = __float_as_uint(As[(r + 8) * GP + k0 + q + 4]);
            }
#pragma unroll
            for (int j = 0; j < 4; j++) {
                int n = wn * 32 + j * 8 + g;
                uint32_t bf0 = __float_as_uint(Bs[n * GP + k0 + q]);
                uint32_t bf1 = __float_as_uint(Bs[n * GP + k0 + q + 4]);
#pragma unroll
                for (int i = 0; i < 4; i++)
                    mma_tf32(acc[i][j], af[i], bf0, bf1);
            }
        }
    }

    // epilogue
#pragma unroll
    for (int i = 0; i < 4; i++) {
        int r0 = bm * 128 + wm * 64 + i * 16 + g;
#pragma unroll
        for (int j = 0; j < 4; j++) {
            int col = bn * 128 + wn * 32 + j * 8 + 2 * q;
            float bx = 0.f, by = 0.f;
            if (bias) { bx = bias[col]; by = bias[col + 1]; }
            float2 v0 = make_float2(acc[i][j][0] + bx, acc[i][j][1] + by);
            float2 v1 = make_float2(acc[i][j][2] + bx, acc[i][j][3] + by);
            *(float2*)&C[(size_t)r0 * N + col] = v0;
            *(float2*)&C[(size_t)(r0 + 8) * N + col] = v1;
        }
    }
}

// ---------------------------------------------------------------------------
// tf32 flash attention. BQ=64, BKV=64, 128 threads (4 warps).
// Warp w owns q-rows [w*16, w*16+16). All mma m16n8k8 tf32.
// Pitches: Qs/Ks/Ps 68 (mod32==4, conflict-free 8x4 reads);
//          Vs 72 (mod32==8, conflict-free 4x8 reads).
// ---------------------------------------------------------------------------
#define QP 68
#define VP 72
#define FLASH_SMEM_FLOATS (64*QP + 64*QP + 64*VP + 64*QP)   // Q,K,V,P = 17664

__global__ __launch_bounds__(128) void flash_tf32_kernel(
    const float* __restrict__ Q, const float* __restrict__ K,
    const float* __restrict__ V, float* __restrict__ O)
{
    extern __shared__ float sm[];
    float* Qs = sm;
    float* Ks = Qs + 64 * QP;
    float* Vs = Ks + 64 * QP;
    float* Ps = Vs + 64 * VP;

    const int tid = threadIdx.x;
    const int warp = tid >> 5, lane = tid & 31;
    const int g = lane >> 2, q = lane & 3;
    const int b = blockIdx.z, h = blockIdx.y;
    const int q0 = blockIdx.x * 64;
    const int base = b * S_ * E_ + h * D_;
    const int r = warp * 16 + g;           // this lane's q-row pair base

    // Load + scale + tf32-convert Q tile [64 q][64 d]
#pragma unroll
    for (int t = 0; t < 8; t++) {
        int u = tid + t * 128;
        int rr = u >> 4, cc = (u & 15) * 4;
        float4 v = *(const float4*)&Q[base + (size_t)(q0 + rr) * E_ + cc];
        float4 o;
        o.x = __uint_as_float(f2tf(v.x * 0.125f));
        o.y = __uint_as_float(f2tf(v.y * 0.125f));
        o.z = __uint_as_float(f2tf(v.z * 0.125f));
        o.w = __uint_as_float(f2tf(v.w * 0.125f));
        *(float4*)&Qs[rr * QP + cc] = o;
    }

    float m0 = -1e30f, m1 = -1e30f, l0 = 0.f, l1 = 0.f;
    float oacc[8][4];
#pragma unroll
    for (int j = 0; j < 8; j++)
#pragma unroll
        for (int t = 0; t < 4; t++) oacc[j][t] = 0.f;

    for (int t0 = 0; t0 < S_; t0 += 64) {
        __syncthreads();   // prior-iter Vs/Ks readers done before overwrite
#pragma unroll
        for (int t = 0; t < 8; t++) {
            int u = tid + t * 128;
            int rr = u >> 4, cc = (u & 15) * 4;
            float4 kv = *(const float4*)&K[base + (size_t)(t0 + rr) * E_ + cc];
            float4 vv = *(const float4*)&V[base + (size_t)(t0 + rr) * E_ + cc];
            float4 ko, vo;
            ko.x = __uint_as_float(f2tf(kv.x)); ko.y = __uint_as_float(f2tf(kv.y));
            ko.z = __uint_as_float(f2tf(kv.z)); ko.w = __uint_as_float(f2tf(kv.w));
            vo.x = __uint_as_float(f2tf(vv.x)); vo.y = __uint_as_float(f2tf(vv.y));
            vo.z = __uint_as_float(f2tf(vv.z)); vo.w = __uint_as_float(f2tf(vv.w));
            *(float4*)&Ks[rr * QP + cc] = ko;
            *(float4*)&Vs[rr * VP + cc] = vo;
        }
        __syncthreads();

        // ---- S = Q @ K^T  (m16 x n64, k=64) ----
        uint32_t af[8][4];
#pragma unroll
        for (int ks = 0; ks < 8; ks++) {
            int k0 = ks * 8;
            af[ks][0] = __float_as_uint(Qs[r * QP + k0 + q]);
            af[ks][1] = __float_as_uint(Qs[(r + 8) * QP + k0 + q]);
            af[ks][2] = __float_as_uint(Qs[r * QP + k0 + q + 4]);
            af[ks][3] = __float_as_uint(Qs[(r + 8) * QP + k0 + q + 4]);
        }
        float sacc[8][4];
#pragma unroll
        for (int j = 0; j < 8; j++) {
#pragma unroll
            for (int t = 0; t < 4; t++) sacc[j][t] = 0.f;
            int n = j * 8 + g;
#pragma unroll
            for (int ks = 0; ks < 8; ks++) {
                int k0 = ks * 8;
                uint32_t b0 = __float_as_uint(Ks[n * QP + k0 + q]);
                uint32_t b1 = __float_as_uint(Ks[n * QP + k0 + q + 4]);
                mma_tf32(sacc[j], af[ks], b0, b1);
            }
        }

        // ---- online softmax (rows r and r+8; reduce across 4 lanes) ----
        float mx0 = -1e30f, mx1 = -1e30f;
#pragma unroll
        for (int j = 0; j < 8; j++) {
            mx0 = fmaxf(mx0, fmaxf(sacc[j][0], sacc[j][1]));
            mx1 = fmaxf(mx1, fmaxf(sacc[j][2], sacc[j][3]));
        }
        mx0 = fmaxf(mx0, __shfl_xor_sync(0xffffffffu, mx0, 1));
        mx0 = fmaxf(mx0, __shfl_xor_sync(0xffffffffu, mx0, 2));
        mx1 = fmaxf(mx1, __shfl_xor_sync(0xffffffffu, mx1, 1));
        mx1 = fmaxf(mx1, __shfl_xor_sync(0xffffffffu, mx1, 2));
        float nm0 = fmaxf(m0, mx0), nm1 = fmaxf(m1, mx1);
        float al0 = __expf(m0 - nm0), al1 = __expf(m1 - nm1);
        m0 = nm0; m1 = nm1;

        float rs0 = 0.f, rs1 = 0.f;
#pragma unroll
        for (int j = 0; j < 8; j++) {
            float p0 = __expf(sacc[j][0] - nm0);
            float p1 = __expf(sacc[j][1] - nm0);
            float p2 = __expf(sacc[j][2] - nm1);
            float p3 = __expf(sacc[j][3] - nm1);
            rs0 += p0 + p1; rs1 += p2 + p3;
            float2 lo = make_float2(__uint_as_float(f2tf(p0)), __uint_as_float(f2tf(p1)));
            float2 hi = make_float2(__uint_as_float(f2tf(p2)), __uint_as_float(f2tf(p3)));
            *(float2*)&Ps[r * QP + j * 8 + 2 * q] = lo;
            *(float2*)&Ps[(r + 8) * QP + j * 8 + 2 * q] = hi;
        }
        rs0 += __shfl_xor_sync(0xffffffffu, rs0, 1);
        rs0 += __shfl_xor_sync(0xffffffffu, rs0, 2);
        rs1 += __shfl_xor_sync(0xffffffffu, rs1, 1);
        rs1 += __shfl_xor_sync(0xffffffffu, rs1, 2);
        l0 = l0 * al0 + rs0;
        l1 = l1 * al1 + rs1;
#pragma unroll
        for (int j = 0; j < 8; j++) {
            oacc[j][0] *= al0; oacc[j][1] *= al0;
            oacc[j][2] *= al1; oacc[j][3] *= al1;
        }
        __syncwarp();

        // ---- O += P @ V  (m16 x n64, k=64) ----
#pragma unroll
        for (int ks = 0; ks < 8; ks++) {
            int k0 = ks * 8;
            af[ks][0] = __float_as_uint(Ps[r * QP + k0 + q]);
            af[ks][1] = __float_as_uint(Ps[(r + 8) * QP + k0 + q]);
            af[ks][2] = __float_as_uint(Ps[r * QP + k0 + q + 4]);
            af[ks][3] = __float_as_uint(Ps[(r + 8) * QP + k0 + q + 4]);
        }
#pragma unroll
        for (int j = 0; j < 8; j++) {
            int n0 = j * 8;
#pragma unroll
            for (int ks = 0; ks < 8; ks++) {
                int k0 = ks * 8;
                uint32_t b0 = __float_as_uint(Vs[(k0 + q) * VP + n0 + g]);
                uint32_t b1 = __float_as_uint(Vs[(k0 + q + 4) * VP + n0 + g]);
                mma_tf32(oacc[j], af[ks], b0, b1);
            }
        }
    }

    // normalize + write ctx in [B,S,H,D] layout
    float inv0 = 1.f / l0, inv1 = 1.f / l1;
#pragma unroll
    for (int j = 0; j < 8; j++) {
        int col = j * 8 + 2 * q;
        float2 lo = make_float2(oacc[j][0] * inv0, oacc[j][1] * inv0);
        float2 hi = make_float2(oacc[j][2] * inv1, oacc[j][3] * inv1);
        *(float2*)&O[base + (size_t)(q0 + r) * E_ + col] = lo;
        *(float2*)&O[base + (size_t)(q0 + r + 8) * E_ + col] = hi;
    }
}

// ---------------------------------------------------------------------------
extern "C" void kernel_launch(void* const* d_in, const int* in_sizes, int n_in,
                              void* d_out, int out_size)
{
    const float* X  = (const float*)d_in[0];
    const float* Wq = (const float*)d_in[1];
    const float* Wk = (const float*)d_in[2];
    const float* Wv = (const float*)d_in[3];
    const float* Wo = (const float*)d_in[4];
    const float* bo = (const float*)d_in[5];
    float* out = (float*)d_out;

    float *Qp, *Kp, *Vp, *Cp;
    cudaGetSymbolAddress((void**)&Qp, g_Q);
    cudaGetSymbolAddress((void**)&Kp, g_K);
    cudaGetSymbolAddress((void**)&Vp, g_V);
    cudaGetSymbolAddress((void**)&Cp, g_Ctx);

    dim3 gemm_grid(E_ / 128, MTOT / 128);   // (8, 64)
    gemm_tf32_nt<<<gemm_grid, 256>>>(X, Wq, nullptr, Qp, MTOT, E_, E_);
    gemm_tf32_nt<<<gemm_grid, 256>>>(X, Wk, nullptr, Kp, MTOT, E_, E_);
    gemm_tf32_nt<<<gemm_grid, 256>>>(X, Wv, nullptr, Vp, MTOT, E_, E_);

    int smem_bytes = FLASH_SMEM_FLOATS * (int)sizeof(float);   // 70656
    cudaFuncSetAttribute(flash_tf32_kernel,
                         cudaFuncAttributeMaxDynamicSharedMemorySize, smem_bytes);
    flash_tf32_kernel<<<dim3(S_ / 64, H_, B_), 128, smem_bytes>>>(Qp, Kp, Vp, Cp);

    gemm_tf32_nt<<<gemm_grid, 256>>>(Cp, Wo, bo, out, MTOT, E_, E_);
}

// round 4
// speedup vs baseline: 2.9521x; 1.0745x over previous
#include <cuda_runtime.h>
#include <cstdint>

#define B_ 4
#define S_ 2048
#define E_ 1024
#define H_ 16
#define D_ 64
#define MTOT (B_*S_)   // 8192

// Scratch (device globals: allocation-free rule)
__device__ float g_Q[B_*S_*E_];
__device__ float g_K[B_*S_*E_];
__device__ float g_V[B_*S_*E_];
__device__ float g_Ctx[B_*S_*E_];

// ---------------------------------------------------------------------------
// helpers
// ---------------------------------------------------------------------------
// HMMA.TF32 truncates fp32 operands to their top 19 bits. Adding 0x1000 to
// the bit pattern before the MMA implements round-to-nearest (ties away):
// 1 IADD instead of a cvt.rna. Low 13 bits are garbage but ignored by HMMA.
__device__ __forceinline__ uint32_t rtf(float x) {
    return __float_as_uint(x) + 0x1000u;
}

__device__ __forceinline__ void mma_tf32(float* c, const uint32_t* a,
                                         uint32_t b0, uint32_t b1) {
    asm volatile(
        "mma.sync.aligned.m16n8k8.row.col.f32.tf32.tf32.f32 "
        "{%0,%1,%2,%3}, {%4,%5,%6,%7}, {%8,%9}, {%0,%1,%2,%3};"
        : "+f"(c[0]), "+f"(c[1]), "+f"(c[2]), "+f"(c[3])
        : "r"(a[0]), "r"(a[1]), "r"(a[2]), "r"(a[3]), "r"(b0), "r"(b1));
}

__device__ __forceinline__ void cp_async16(uint32_t saddr, const void* g) {
    asm volatile("cp.async.cg.shared.global [%0], [%1], 16;"
                 :: "r"(saddr), "l"(g));
}
__device__ __forceinline__ void cp_commit() {
    asm volatile("cp.async.commit_group;");
}
template <int N>
__device__ __forceinline__ void cp_wait() {
    asm volatile("cp.async.wait_group %0;" :: "n"(N));
}

// ---------------------------------------------------------------------------
// tf32 GEMM (NT): C[m,n] = sum_k A[m,k]*B[n,k] (+ bias[n])
// CTA 128x128, BK=16, 256 thr (8 warps, 2x4), warp tile 64x32.
// cp.async double-buffered staging (raw fp32); RN rounding applied at
// fragment load via +0x1000 IADD. smem pitch 20: conflict-free frag reads.
// ---------------------------------------------------------------------------
#define GP 20
__global__ __launch_bounds__(256) void gemm_tf32_nt(
    const float* __restrict__ A, const float* __restrict__ Bm,
    const float* __restrict__ bias, float* __restrict__ C,
    int M, int N, int K)
{
    __shared__ float As[2][128 * GP];
    __shared__ float Bs[2][128 * GP];

    const int tid = threadIdx.x;
    const int warp = tid >> 5, lane = tid & 31;
    const int g = lane >> 2, q = lane & 3;
    const int wm = warp >> 2;          // 0..1
    const int wn = warp & 3;           // 0..3
    const int bm = blockIdx.y, bn = blockIdx.x;

    const int lrow = tid >> 1;
    const int lcol = (tid & 1) * 8;
    const float* Ap = A + (size_t)(bm * 128 + lrow) * K + lcol;
    const float* Bp = Bm + (size_t)(bn * 128 + lrow) * K + lcol;

    uint32_t sA0 = (uint32_t)__cvta_generic_to_shared(&As[0][lrow * GP + lcol]);
    uint32_t sB0 = (uint32_t)__cvta_generic_to_shared(&Bs[0][lrow * GP + lcol]);
    const uint32_t stg = (uint32_t)(128 * GP * sizeof(float));

    float acc[4][4][4];
#pragma unroll
    for (int i = 0; i < 4; i++)
#pragma unroll
        for (int j = 0; j < 4; j++)
#pragma unroll
            for (int t = 0; t < 4; t++) acc[i][j][t] = 0.f;

    const int nt = K / 16;
    cp_async16(sA0, Ap);
    cp_async16(sA0 + 16, Ap + 4);
    cp_async16(sB0, Bp);
    cp_async16(sB0 + 16, Bp + 4);
    cp_commit();

    for (int kt = 0; kt < nt; kt++) {
        const int cur = kt & 1;
        if (kt + 1 < nt) {
            const int nxt = (kt + 1) & 1;
            const float* ap = Ap + (kt + 1) * 16;
            const float* bp = Bp + (kt + 1) * 16;
            cp_async16(sA0 + nxt * stg, ap);
            cp_async16(sA0 + nxt * stg + 16, ap + 4);
            cp_async16(sB0 + nxt * stg, bp);
            cp_async16(sB0 + nxt * stg + 16, bp + 4);
            cp_commit();
            cp_wait<1>();
        } else {
            cp_wait<0>();
        }
        __syncthreads();

        const float* as = As[cur];
        const float* bs = Bs[cur];
#pragma unroll
        for (int kh = 0; kh < 2; kh++) {
            const int k0 = kh * 8;
            uint32_t af[4][4];
#pragma unroll
            for (int i = 0; i < 4; i++) {
                int r = wm * 64 + i * 16 + g;
                af[i][0] = rtf(as[r * GP + k0 + q]);
                af[i][1] = rtf(as[(r + 8) * GP + k0 + q]);
                af[i][2] = rtf(as[r * GP + k0 + q + 4]);
                af[i][3] = rtf(as[(r + 8) * GP + k0 + q + 4]);
            }
#pragma unroll
            for (int j = 0; j < 4; j++) {
                int n = wn * 32 + j * 8 + g;
                uint32_t bf0 = rtf(bs[n * GP + k0 + q]);
                uint32_t bf1 = rtf(bs[n * GP + k0 + q + 4]);
#pragma unroll
                for (int i = 0; i < 4; i++)
                    mma_tf32(acc[i][j], af[i], bf0, bf1);
            }
        }
        __syncthreads();
    }

    // epilogue
#pragma unroll
    for (int i = 0; i < 4; i++) {
        int r0 = bm * 128 + wm * 64 + i * 16 + g;
#pragma unroll
        for (int j = 0; j < 4; j++) {
            int col = bn * 128 + wn * 32 + j * 8 + 2 * q;
            float bx = 0.f, by = 0.f;
            if (bias) { bx = bias[col]; by = bias[col + 1]; }
            float2 v0 = make_float2(acc[i][j][0] + bx, acc[i][j][1] + by);
            float2 v1 = make_float2(acc[i][j][2] + bx, acc[i][j][3] + by);
            *(float2*)&C[(size_t)r0 * N + col] = v0;
            *(float2*)&C[(size_t)(r0 + 8) * N + col] = v1;
        }
    }
}

// ---------------------------------------------------------------------------
// tf32 flash attention. BQ=64, BKV=64, 128 threads (4 warps).
// Warp w owns q-rows [w*16, w*16+16). Q fragments hoisted (loop-invariant).
// RN rounding applied at smem STAGING time (each smem value consumed 4x).
// Q staged through Ps (rows warp-private -> no hazard).
// Pitches: Ks/Ps 68 (mod32==4), Vs 72 (mod32==8): conflict-free frag reads.
// smem = 53248 B -> 4 CTAs/SM.
// ---------------------------------------------------------------------------
#define QP 68
#define VP 72
#define FLASH_SMEM_FLOATS (64*QP + 64*VP + 64*QP)   // K,V,P = 13312

__global__ __launch_bounds__(128) void flash_tf32_kernel(
    const float* __restrict__ Q, const float* __restrict__ K,
    const float* __restrict__ V, float* __restrict__ O)
{
    extern __shared__ float sm[];
    float* Ks = sm;
    float* Vs = Ks + 64 * QP;
    float* Ps = Vs + 64 * VP;

    const int tid = threadIdx.x;
    const int warp = tid >> 5, lane = tid & 31;
    const int g = lane >> 2, q = lane & 3;
    const int b = blockIdx.z, h = blockIdx.y;
    const int q0 = blockIdx.x * 64;
    const int base = b * S_ * E_ + h * D_;
    const int r = warp * 16 + g;           // this lane's q-row pair base

    // Stage Q tile (scaled by 1/8 exact, then RN-biased) through Ps.
#pragma unroll
    for (int t = 0; t < 8; t++) {
        int u = tid + t * 128;
        int rr = u >> 4, cc = (u & 15) * 4;
        float4 v = *(const float4*)&Q[base + (size_t)(q0 + rr) * E_ + cc];
        uint4 o;
        o.x = rtf(v.x * 0.125f); o.y = rtf(v.y * 0.125f);
        o.z = rtf(v.z * 0.125f); o.w = rtf(v.w * 0.125f);
        *(uint4*)&Ps[rr * QP + cc] = o;
    }
    __syncthreads();

    uint32_t aq[8][4];
#pragma unroll
    for (int ks = 0; ks < 8; ks++) {
        int k0 = ks * 8;
        aq[ks][0] = __float_as_uint(Ps[r * QP + k0 + q]);
        aq[ks][1] = __float_as_uint(Ps[(r + 8) * QP + k0 + q]);
        aq[ks][2] = __float_as_uint(Ps[r * QP + k0 + q + 4]);
        aq[ks][3] = __float_as_uint(Ps[(r + 8) * QP + k0 + q + 4]);
    }

    float m0 = -1e30f, m1 = -1e30f, l0 = 0.f, l1 = 0.f;
    float oacc[8][4];
#pragma unroll
    for (int j = 0; j < 8; j++)
#pragma unroll
        for (int t = 0; t < 4; t++) oacc[j][t] = 0.f;

    for (int t0 = 0; t0 < S_; t0 += 64) {
        __syncthreads();   // prior-iter Ks/Vs readers done before overwrite
#pragma unroll
        for (int t = 0; t < 8; t++) {
            int u = tid + t * 128;
            int rr = u >> 4, cc = (u & 15) * 4;
            float4 kv = *(const float4*)&K[base + (size_t)(t0 + rr) * E_ + cc];
            float4 vv = *(const float4*)&V[base + (size_t)(t0 + rr) * E_ + cc];
            uint4 ko, vo;
            ko.x = rtf(kv.x); ko.y = rtf(kv.y); ko.z = rtf(kv.z); ko.w = rtf(kv.w);
            vo.x = rtf(vv.x); vo.y = rtf(vv.y); vo.z = rtf(vv.z); vo.w = rtf(vv.w);
            *(uint4*)&Ks[rr * QP + cc] = ko;
            *(uint4*)&Vs[rr * VP + cc] = vo;
        }
        __syncthreads();

        // ---- S = Q @ K^T  (m16 x n64, k=64) ----
        float sacc[8][4];
#pragma unroll
        for (int j = 0; j < 8; j++) {
#pragma unroll
            for (int t = 0; t < 4; t++) sacc[j][t] = 0.f;
            int n = j * 8 + g;
#pragma unroll
            for (int ks = 0; ks < 8; ks++) {
                int k0 = ks * 8;
                uint32_t b0 = __float_as_uint(Ks[n * QP + k0 + q]);
                uint32_t b1 = __float_as_uint(Ks[n * QP + k0 + q + 4]);
                mma_tf32(sacc[j], aq[ks], b0, b1);
            }
        }

        // ---- online softmax (rows r and r+8; reduce across 4 lanes) ----
        float mx0 = -1e30f, mx1 = -1e30f;
#pragma unroll
        for (int j = 0; j < 8; j++) {
            mx0 = fmaxf(mx0, fmaxf(sacc[j][0], sacc[j][1]));
            mx1 = fmaxf(mx1, fmaxf(sacc[j][2], sacc[j][3]));
        }
        mx0 = fmaxf(mx0, __shfl_xor_sync(0xffffffffu, mx0, 1));
        mx0 = fmaxf(mx0, __shfl_xor_sync(0xffffffffu, mx0, 2));
        mx1 = fmaxf(mx1, __shfl_xor_sync(0xffffffffu, mx1, 1));
        mx1 = fmaxf(mx1, __shfl_xor_sync(0xffffffffu, mx1, 2));
        float nm0 = fmaxf(m0, mx0), nm1 = fmaxf(m1, mx1);
        float al0 = __expf(m0 - nm0), al1 = __expf(m1 - nm1);
        m0 = nm0; m1 = nm1;

        float rs0 = 0.f, rs1 = 0.f;
#pragma unroll
        for (int j = 0; j < 8; j++) {
            float p0 = __expf(sacc[j][0] - nm0);
            float p1 = __expf(sacc[j][1] - nm0);
            float p2 = __expf(sacc[j][2] - nm1);
            float p3 = __expf(sacc[j][3] - nm1);
            rs0 += p0 + p1; rs1 += p2 + p3;
            uint2 lo = make_uint2(rtf(p0), rtf(p1));
            uint2 hi = make_uint2(rtf(p2), rtf(p3));
            *(uint2*)&Ps[r * QP + j * 8 + 2 * q] = lo;
            *(uint2*)&Ps[(r + 8) * QP + j * 8 + 2 * q] = hi;
        }
        rs0 += __shfl_xor_sync(0xffffffffu, rs0, 1);
        rs0 += __shfl_xor_sync(0xffffffffu, rs0, 2);
        rs1 += __shfl_xor_sync(0xffffffffu, rs1, 1);
        rs1 += __shfl_xor_sync(0xffffffffu, rs1, 2);
        l0 = l0 * al0 + rs0;
        l1 = l1 * al1 + rs1;
#pragma unroll
        for (int j = 0; j < 8; j++) {
            oacc[j][0] *= al0; oacc[j][1] *= al0;
            oacc[j][2] *= al1; oacc[j][3] *= al1;
        }
        __syncwarp();   // own-warp Ps writes -> own-warp frag reads

        // ---- O += P @ V  (m16 x n64, k=64) ----
        uint32_t ap[4];
#pragma unroll
        for (int ks = 0; ks < 8; ks++) {
            int k0 = ks * 8;
            ap[0] = __float_as_uint(Ps[r * QP + k0 + q]);
            ap[1] = __float_as_uint(Ps[(r + 8) * QP + k0 + q]);
            ap[2] = __float_as_uint(Ps[r * QP + k0 + q + 4]);
            ap[3] = __float_as_uint(Ps[(r + 8) * QP + k0 + q + 4]);
#pragma unroll
            for (int j = 0; j < 8; j++) {
                uint32_t b0 = __float_as_uint(Vs[(k0 + q) * VP + j * 8 + g]);
                uint32_t b1 = __float_as_uint(Vs[(k0 + q + 4) * VP + j * 8 + g]);
                mma_tf32(oacc[j], ap, b0, b1);
            }
        }
    }

    // normalize + write ctx in [B,S,H,D] layout
    float inv0 = 1.f / l0, inv1 = 1.f / l1;
#pragma unroll
    for (int j = 0; j < 8; j++) {
        int col = j * 8 + 2 * q;
        float2 lo = make_float2(oacc[j][0] * inv0, oacc[j][1] * inv0);
        float2 hi = make_float2(oacc[j][2] * inv1, oacc[j][3] * inv1);
        *(float2*)&O[base + (size_t)(q0 + r) * E_ + col] = lo;
        *(float2*)&O[base + (size_t)(q0 + r + 8) * E_ + col] = hi;
    }
}

// ---------------------------------------------------------------------------
extern "C" void kernel_launch(void* const* d_in, const int* in_sizes, int n_in,
                              void* d_out, int out_size)
{
    const float* X  = (const float*)d_in[0];
    const float* Wq = (const float*)d_in[1];
    const float* Wk = (const float*)d_in[2];
    const float* Wv = (const float*)d_in[3];
    const float* Wo = (const float*)d_in[4];
    const float* bo = (const float*)d_in[5];
    float* out = (float*)d_out;

    float *Qp, *Kp, *Vp, *Cp;
    cudaGetSymbolAddress((void**)&Qp, g_Q);
    cudaGetSymbolAddress((void**)&Kp, g_K);
    cudaGetSymbolAddress((void**)&Vp, g_V);
    cudaGetSymbolAddress((void**)&Cp, g_Ctx);

    dim3 gemm_grid(E_ / 128, MTOT / 128);   // (8, 64)
    gemm_tf32_nt<<<gemm_grid, 256>>>(X, Wq, nullptr, Qp, MTOT, E_, E_);
    gemm_tf32_nt<<<gemm_grid, 256>>>(X, Wk, nullptr, Kp, MTOT, E_, E_);
    gemm_tf32_nt<<<gemm_grid, 256>>>(X, Wv, nullptr, Vp, MTOT, E_, E_);

    int smem_bytes = FLASH_SMEM_FLOATS * (int)sizeof(float);   // 53248
    cudaFuncSetAttribute(flash_tf32_kernel,
                         cudaFuncAttributeMaxDynamicSharedMemorySize, smem_bytes);
    flash_tf32_kernel<<<dim3(S_ / 64, H_, B_), 128, smem_bytes>>>(Qp, Kp, Vp, Cp);

    gemm_tf32_nt<<<gemm_grid, 256>>>(Cp, Wo, bo, out, MTOT, E_, E_);
}

// round 6
// speedup vs baseline: 3.3832x; 1.1460x over previous
#include <cuda_runtime.h>
#include <cstdint>

#define B_ 4
#define S_ 2048
#define E_ 1024
#define H_ 16
#define D_ 64
#define MTOT (B_*S_)   // 8192

// Scratch (device globals: allocation-free rule)
__device__ float g_Q[B_*S_*E_];
__device__ float g_K[B_*S_*E_];
__device__ float g_V[B_*S_*E_];
__device__ float g_Ctx[B_*S_*E_];

// ---------------------------------------------------------------------------
// helpers
// ---------------------------------------------------------------------------
// HMMA.TF32 reads the top 19 bits of an fp32 register. +0x1000 on the bit
// pattern = round-to-nearest (ties away) in 1 IADD. (== cvt.rna numerics.)
__device__ __forceinline__ uint32_t rtf(float x) {
    return __float_as_uint(x) + 0x1000u;
}

__device__ __forceinline__ void mma_tf32(float* c, const uint32_t* a,
                                         uint32_t b0, uint32_t b1) {
    asm volatile(
        "mma.sync.aligned.m16n8k8.row.col.f32.tf32.tf32.f32 "
        "{%0,%1,%2,%3}, {%4,%5,%6,%7}, {%8,%9}, {%0,%1,%2,%3};"
        : "+f"(c[0]), "+f"(c[1]), "+f"(c[2]), "+f"(c[3])
        : "r"(a[0]), "r"(a[1]), "r"(a[2]), "r"(a[3]), "r"(b0), "r"(b1));
}

__device__ __forceinline__ void cp_async16(uint32_t saddr, const void* g) {
    asm volatile("cp.async.cg.shared.global [%0], [%1], 16;"
                 :: "r"(saddr), "l"(g));
}
__device__ __forceinline__ void cp_commit() {
    asm volatile("cp.async.commit_group;");
}
template <int N>
__device__ __forceinline__ void cp_wait() {
    asm volatile("cp.async.wait_group %0;" :: "n"(N));
}

// ---------------------------------------------------------------------------
// tf32 GEMM (NT): C[m,n] = sum_k A[m,k]*B[n,k] (+ bias[n])
// CTA 128x128, BK=16, 256 thr (8 warps, 2x4), warp tile 64x32.
// 3-stage cp.async pipeline, ONE __syncthreads per k-tile.
// RN rounding at fragment load (+0x1000). smem pitch 20: conflict-free.
// ---------------------------------------------------------------------------
#define GP 20
#define GSTG (128 * GP)
#define GEMM_SMEM_FLOATS (6 * GSTG)   // As[3] + Bs[3] = 61440 B

__global__ __launch_bounds__(256) void gemm_tf32_nt(
    const float* __restrict__ A, const float* __restrict__ Bm,
    const float* __restrict__ bias, float* __restrict__ C,
    int M, int N, int K)
{
    extern __shared__ float smg[];
    float* As = smg;             // 3 buffers of GSTG
    float* Bs = smg + 3 * GSTG;

    const int tid = threadIdx.x;
    const int warp = tid >> 5, lane = tid & 31;
    const int g = lane >> 2, q = lane & 3;
    const int wm = warp >> 2;          // 0..1
    const int wn = warp & 3;           // 0..3
    const int bm = blockIdx.y, bn = blockIdx.x;

    const int lrow = tid >> 1;
    const int lcol = (tid & 1) * 8;
    const float* Ap = A + (size_t)(bm * 128 + lrow) * K + lcol;
    const float* Bp = Bm + (size_t)(bn * 128 + lrow) * K + lcol;

    uint32_t sA0 = (uint32_t)__cvta_generic_to_shared(&As[lrow * GP + lcol]);
    uint32_t sB0 = (uint32_t)__cvta_generic_to_shared(&Bs[lrow * GP + lcol]);
    const uint32_t stg = (uint32_t)(GSTG * sizeof(float));

    float acc[4][4][4];
#pragma unroll
    for (int i = 0; i < 4; i++)
#pragma unroll
        for (int j = 0; j < 4; j++)
#pragma unroll
            for (int t = 0; t < 4; t++) acc[i][j][t] = 0.f;

    const int nt = K / 16;
    // prologue: stage tiles 0 and 1 into bufs 0 and 1
#pragma unroll
    for (int p = 0; p < 2; p++) {
        const float* ap = Ap + p * 16;
        const float* bp = Bp + p * 16;
        cp_async16(sA0 + p * stg, ap);
        cp_async16(sA0 + p * stg + 16, ap + 4);
        cp_async16(sB0 + p * stg, bp);
        cp_async16(sB0 + p * stg + 16, bp + 4);
        cp_commit();
    }

    for (int kt = 0; kt < nt; kt++) {
        const int cur = kt % 3;
        cp_wait<1>();          // tile kt resident
        __syncthreads();       // also: readers of buf (kt+2)%3 (from kt-1) done
        if (kt + 2 < nt) {
            const int nxt = (kt + 2) % 3;
            const float* ap = Ap + (kt + 2) * 16;
            const float* bp = Bp + (kt + 2) * 16;
            cp_async16(sA0 + nxt * stg, ap);
            cp_async16(sA0 + nxt * stg + 16, ap + 4);
            cp_async16(sB0 + nxt * stg, bp);
            cp_async16(sB0 + nxt * stg + 16, bp + 4);
            cp_commit();
        } else {
            cp_commit();       // empty group keeps count in step for cp_wait<1>
        }

        const float* as = As + cur * GSTG;
        const float* bs = Bs + cur * GSTG;
#pragma unroll
        for (int kh = 0; kh < 2; kh++) {
            const int k0 = kh * 8;
            uint32_t af[4][4];
#pragma unroll
            for (int i = 0; i < 4; i++) {
                int r = wm * 64 + i * 16 + g;
                af[i][0] = rtf(as[r * GP + k0 + q]);
                af[i][1] = rtf(as[(r + 8) * GP + k0 + q]);
                af[i][2] = rtf(as[r * GP + k0 + q + 4]);
                af[i][3] = rtf(as[(r + 8) * GP + k0 + q + 4]);
            }
#pragma unroll
            for (int j = 0; j < 4; j++) {
                int n = wn * 32 + j * 8 + g;
                uint32_t bf0 = rtf(bs[n * GP + k0 + q]);
                uint32_t bf1 = rtf(bs[n * GP + k0 + q + 4]);
#pragma unroll
                for (int i = 0; i < 4; i++)
                    mma_tf32(acc[i][j], af[i], bf0, bf1);
            }
        }
    }

    // epilogue
#pragma unroll
    for (int i = 0; i < 4; i++) {
        int r0 = bm * 128 + wm * 64 + i * 16 + g;
#pragma unroll
        for (int j = 0; j < 4; j++) {
            int col = bn * 128 + wn * 32 + j * 8 + 2 * q;
            float bx = 0.f, by = 0.f;
            if (bias) { bx = bias[col]; by = bias[col + 1]; }
            float2 v0 = make_float2(acc[i][j][0] + bx, acc[i][j][1] + by);
            float2 v1 = make_float2(acc[i][j][2] + bx, acc[i][j][3] + by);
            *(float2*)&C[(size_t)r0 * N + col] = v0;
            *(float2*)&C[(size_t)(r0 + 8) * N + col] = v1;
        }
    }
}

// ---------------------------------------------------------------------------
// tf32 flash attention. BQ=128, BKV=64, 128 threads (4 warps).
// Warp w owns q-rows [w*32, w*32+32) = TWO m16 tiles -> every K/V fragment
// LDS feeds 2 MMAs (smem bytes per FLOP cut 33% vs m16 warps).
// RN rounding at smem staging. Pitches: Qs/Ks/Ps 68, Vs 72 (conflict-free).
// smem = 105472 B -> 2 CTAs/SM.
// ---------------------------------------------------------------------------
#define QP 68
#define VP 72
#define FLASH_SMEM_FLOATS (128*QP + 64*QP + 64*VP + 128*QP)   // 26368

__global__ __launch_bounds__(128) void flash_tf32_kernel(
    const float* __restrict__ Q, const float* __restrict__ K,
    const float* __restrict__ V, float* __restrict__ O)
{
    extern __shared__ float sm[];
    float* Qs = sm;                    // [128][QP]
    float* Ks = Qs + 128 * QP;         // [64][QP]
    float* Vs = Ks + 64 * QP;          // [64][VP]
    float* Ps = Vs + 64 * VP;          // [128][QP]

    const int tid = threadIdx.x;
    const int warp = tid >> 5, lane = tid & 31;
    const int g = lane >> 2, q = lane & 3;
    const int b = blockIdx.z, h = blockIdx.y;
    const int q0 = blockIdx.x * 128;
    const int base = b * S_ * E_ + h * D_;
    const int r0 = warp * 32 + g;      // m-tile 0 row base
    const int r1 = r0 + 16;            // m-tile 1 row base

    // Stage Q tile [128 q][64 d], scaled by 1/8 (exact) + RN bias.
#pragma unroll
    for (int t = 0; t < 16; t++) {
        int u = tid + t * 128;
        int rr = u >> 4, cc = (u & 15) * 4;
        float4 v = *(const float4*)&Q[base + (size_t)(q0 + rr) * E_ + cc];
        uint4 o;
        o.x = rtf(v.x * 0.125f); o.y = rtf(v.y * 0.125f);
        o.z = rtf(v.z * 0.125f); o.w = rtf(v.w * 0.125f);
        *(uint4*)&Qs[rr * QP + cc] = o;
    }

    float m0a = -1e30f, m0b = -1e30f, m1a = -1e30f, m1b = -1e30f;
    float l0a = 0.f, l0b = 0.f, l1a = 0.f, l1b = 0.f;
    float oacc0[8][4], oacc1[8][4];
#pragma unroll
    for (int j = 0; j < 8; j++)
#pragma unroll
        for (int t = 0; t < 4; t++) { oacc0[j][t] = 0.f; oacc1[j][t] = 0.f; }

    for (int t0 = 0; t0 < S_; t0 += 64) {
        __syncthreads();   // prior-iter Ks/Vs readers done; also covers Qs init
        // K/V tiles are 64x64 = 4096 floats; 8 iters x 128 thr x float4.
#pragma unroll
        for (int t = 0; t < 8; t++) {
            int u = tid + t * 128;
            int rr = u >> 4, cc = (u & 15) * 4;
            float4 kv = *(const float4*)&K[base + (size_t)(t0 + rr) * E_ + cc];
            float4 vv = *(const float4*)&V[base + (size_t)(t0 + rr) * E_ + cc];
            uint4 ko, vo;
            ko.x = rtf(kv.x); ko.y = rtf(kv.y); ko.z = rtf(kv.z); ko.w = rtf(kv.w);
            vo.x = rtf(vv.x); vo.y = rtf(vv.y); vo.z = rtf(vv.z); vo.w = rtf(vv.w);
            *(uint4*)&Ks[rr * QP + cc] = ko;
            *(uint4*)&Vs[rr * VP + cc] = vo;
        }
        __syncthreads();

        // ---- S = Q @ K^T  (m32 x n64, k=64): K frags shared by 2 m-tiles --
        float s0[8][4], s1[8][4];
#pragma unroll
        for (int j = 0; j < 8; j++)
#pragma unroll
            for (int t = 0; t < 4; t++) { s0[j][t] = 0.f; s1[j][t] = 0.f; }

#pragma unroll
        for (int ks = 0; ks < 8; ks++) {
            int k0 = ks * 8;
            uint32_t a0[4], a1[4];
            a0[0] = __float_as_uint(Qs[r0 * QP + k0 + q]);
            a0[1] = __float_as_uint(Qs[(r0 + 8) * QP + k0 + q]);
            a0[2] = __float_as_uint(Qs[r0 * QP + k0 + q + 4]);
            a0[3] = __float_as_uint(Qs[(r0 + 8) * QP + k0 + q + 4]);
            a1[0] = __float_as_uint(Qs[r1 * QP + k0 + q]);
            a1[1] = __float_as_uint(Qs[(r1 + 8) * QP + k0 + q]);
            a1[2] = __float_as_uint(Qs[r1 * QP + k0 + q + 4]);
            a1[3] = __float_as_uint(Qs[(r1 + 8) * QP + k0 + q + 4]);
#pragma unroll
            for (int j = 0; j < 8; j++) {
                int n = j * 8 + g;
                uint32_t b0 = __float_as_uint(Ks[n * QP + k0 + q]);
                uint32_t b1 = __float_as_uint(Ks[n * QP + k0 + q + 4]);
                mma_tf32(s0[j], a0, b0, b1);
                mma_tf32(s1[j], a1, b0, b1);
            }
        }

        // ---- online softmax, m-tile 0 (rows r0, r0+8) ----
        {
            float mxa = -1e30f, mxb = -1e30f;
#pragma unroll
            for (int j = 0; j < 8; j++) {
                mxa = fmaxf(mxa, fmaxf(s0[j][0], s0[j][1]));
                mxb = fmaxf(mxb, fmaxf(s0[j][2], s0[j][3]));
            }
            mxa = fmaxf(mxa, __shfl_xor_sync(0xffffffffu, mxa, 1));
            mxa = fmaxf(mxa, __shfl_xor_sync(0xffffffffu, mxa, 2));
            mxb = fmaxf(mxb, __shfl_xor_sync(0xffffffffu, mxb, 1));
            mxb = fmaxf(mxb, __shfl_xor_sync(0xffffffffu, mxb, 2));
            float nma = fmaxf(m0a, mxa), nmb = fmaxf(m0b, mxb);
            float ala = __expf(m0a - nma), alb = __expf(m0b - nmb);
            m0a = nma; m0b = nmb;
            float rsa = 0.f, rsb = 0.f;
#pragma unroll
            for (int j = 0; j < 8; j++) {
                float p0 = __expf(s0[j][0] - nma);
                float p1 = __expf(s0[j][1] - nma);
                float p2 = __expf(s0[j][2] - nmb);
                float p3 = __expf(s0[j][3] - nmb);
                rsa += p0 + p1; rsb += p2 + p3;
                *(uint2*)&Ps[r0 * QP + j * 8 + 2 * q] = make_uint2(rtf(p0), rtf(p1));
                *(uint2*)&Ps[(r0 + 8) * QP + j * 8 + 2 * q] = make_uint2(rtf(p2), rtf(p3));
            }
            rsa += __shfl_xor_sync(0xffffffffu, rsa, 1);
            rsa += __shfl_xor_sync(0xffffffffu, rsa, 2);
            rsb += __shfl_xor_sync(0xffffffffu, rsb, 1);
            rsb += __shfl_xor_sync(0xffffffffu, rsb, 2);
            l0a = l0a * ala + rsa;
            l0b = l0b * alb + rsb;
#pragma unroll
            for (int j = 0; j < 8; j++) {
                oacc0[j][0] *= ala; oacc0[j][1] *= ala;
                oacc0[j][2] *= alb; oacc0[j][3] *= alb;
            }
        }

        // ---- online softmax, m-tile 1 (rows r1, r1+8) ----
        {
            float mxa = -1e30f, mxb = -1e30f;
#pragma unroll
            for (int j = 0; j < 8; j++) {
                mxa = fmaxf(mxa, fmaxf(s1[j][0], s1[j][1]));
                mxb = fmaxf(mxb, fmaxf(s1[j][2], s1[j][3]));
            }
            mxa = fmaxf(mxa, __shfl_xor_sync(0xffffffffu, mxa, 1));
            mxa = fmaxf(mxa, __shfl_xor_sync(0xffffffffu, mxa, 2));
            mxb = fmaxf(mxb, __shfl_xor_sync(0xffffffffu, mxb, 1));
            mxb = fmaxf(mxb, __shfl_xor_sync(0xffffffffu, mxb, 2));
            float nma = fmaxf(m1a, mxa), nmb = fmaxf(m1b, mxb);
            float ala = __expf(m1a - nma), alb = __expf(m1b - nmb);
            m1a = nma; m1b = nmb;
            float rsa = 0.f, rsb = 0.f;
#pragma unroll
            for (int j = 0; j < 8; j++) {
                float p0 = __expf(s1[j][0] - nma);
                float p1 = __expf(s1[j][1] - nma);
                float p2 = __expf(s1[j][2] - nmb);
                float p3 = __expf(s1[j][3] - nmb);
                rsa += p0 + p1; rsb += p2 + p3;
                *(uint2*)&Ps[r1 * QP + j * 8 + 2 * q] = make_uint2(rtf(p0), rtf(p1));
                *(uint2*)&Ps[(r1 + 8) * QP + j * 8 + 2 * q] = make_uint2(rtf(p2), rtf(p3));
            }
            rsa += __shfl_xor_sync(0xffffffffu, rsa, 1);
            rsa += __shfl_xor_sync(0xffffffffu, rsa, 2);
            rsb += __shfl_xor_sync(0xffffffffu, rsb, 1);
            rsb += __shfl_xor_sync(0xffffffffu, rsb, 2);
            l1a = l1a * ala + rsa;
            l1b = l1b * alb + rsb;
#pragma unroll
            for (int j = 0; j < 8; j++) {
                oacc1[j][0] *= ala; oacc1[j][1] *= ala;
                oacc1[j][2] *= alb; oacc1[j][3] *= alb;
            }
        }
        __syncwarp();   // own-warp Ps writes -> own-warp frag reads

        // ---- O += P @ V  (m32 x n64, k=64): V frags shared by 2 m-tiles --
#pragma unroll
        for (int ks = 0; ks < 8; ks++) {
            int k0 = ks * 8;
            uint32_t a0[4], a1[4];
            a0[0] = __float_as_uint(Ps[r0 * QP + k0 + q]);
            a0[1] = __float_as_uint(Ps[(r0 + 8) * QP + k0 + q]);
            a0[2] = __float_as_uint(Ps[r0 * QP + k0 + q + 4]);
            a0[3] = __float_as_uint(Ps[(r0 + 8) * QP + k0 + q + 4]);
            a1[0] = __float_as_uint(Ps[r1 * QP + k0 + q]);
            a1[1] = __float_as_uint(Ps[(r1 + 8) * QP + k0 + q]);
            a1[2] = __float_as_uint(Ps[r1 * QP + k0 + q + 4]);
            a1[3] = __float_as_uint(Ps[(r1 + 8) * QP + k0 + q + 4]);
#pragma unroll
            for (int j = 0; j < 8; j++) {
                uint32_t b0 = __float_as_uint(Vs[(k0 + q) * VP + j * 8 + g]);
                uint32_t b1 = __float_as_uint(Vs[(k0 + q + 4) * VP + j * 8 + g]);
                mma_tf32(oacc0[j], a0, b0, b1);
                mma_tf32(oacc1[j], a1, b0, b1);
            }
        }
    }

    // normalize + write ctx in [B,S,H,D] layout
    float i0a = 1.f / l0a, i0b = 1.f / l0b, i1a = 1.f / l1a, i1b = 1.f / l1b;
#pragma unroll
    for (int j = 0; j < 8; j++) {
        int col = j * 8 + 2 * q;
        *(float2*)&O[base + (size_t)(q0 + r0) * E_ + col] =
            make_float2(oacc0[j][0] * i0a, oacc0[j][1] * i0a);
        *(float2*)&O[base + (size_t)(q0 + r0 + 8) * E_ + col] =
            make_float2(oacc0[j][2] * i0b, oacc0[j][3] * i0b);
        *(float2*)&O[base + (size_t)(q0 + r1) * E_ + col] =
            make_float2(oacc1[j][0] * i1a, oacc1[j][1] * i1a);
        *(float2*)&O[base + (size_t)(q0 + r1 + 8) * E_ + col] =
            make_float2(oacc1[j][2] * i1b, oacc1[j][3] * i1b);
    }
}

// ---------------------------------------------------------------------------
extern "C" void kernel_launch(void* const* d_in, const int* in_sizes, int n_in,
                              void* d_out, int out_size)
{
    const float* X  = (const float*)d_in[0];
    const float* Wq = (const float*)d_in[1];
    const float* Wk = (const float*)d_in[2];
    const float* Wv = (const float*)d_in[3];
    const float* Wo = (const float*)d_in[4];
    const float* bo = (const float*)d_in[5];
    float* out = (float*)d_out;

    float *Qp, *Kp, *Vp, *Cp;
    cudaGetSymbolAddress((void**)&Qp, g_Q);
    cudaGetSymbolAddress((void**)&Kp, g_K);
    cudaGetSymbolAddress((void**)&Vp, g_V);
    cudaGetSymbolAddress((void**)&Cp, g_Ctx);

    int gemm_smem = GEMM_SMEM_FLOATS * (int)sizeof(float);   // 61440
    cudaFuncSetAttribute(gemm_tf32_nt,
                         cudaFuncAttributeMaxDynamicSharedMemorySize, gemm_smem);
    int flash_smem = FLASH_SMEM_FLOATS * (int)sizeof(float); // 105472
    cudaFuncSetAttribute(flash_tf32_kernel,
                         cudaFuncAttributeMaxDynamicSharedMemorySize, flash_smem);

    dim3 gemm_grid(E_ / 128, MTOT / 128);   // (8, 64)
    gemm_tf32_nt<<<gemm_grid, 256, gemm_smem>>>(X, Wq, nullptr, Qp, MTOT, E_, E_);
    gemm_tf32_nt<<<gemm_grid, 256, gemm_smem>>>(X, Wk, nullptr, Kp, MTOT, E_, E_);
    gemm_tf32_nt<<<gemm_grid, 256, gemm_smem>>>(X, Wv, nullptr, Vp, MTOT, E_, E_);

    flash_tf32_kernel<<<dim3(S_ / 128, H_, B_), 128, flash_smem>>>(Qp, Kp, Vp, Cp);

    gemm_tf32_nt<<<gemm_grid, 256, gemm_smem>>>(Cp, Wo, bo, out, MTOT, E_, E_);
}